// round 2
// baseline (speedup 1.0000x reference)
#include <cuda_runtime.h>
#include <cstdint>
#include <cstddef>
#include <math.h>

#define NN 100000
#define EE 1600000
#define ETOT (EE + NN)

// ---------------- scratch (device globals; no runtime allocation) ----------
__device__ __align__(16) float g_h[(size_t)NN * 128];     // GEMM output (per layer)
__device__ __align__(16) float g_out[(size_t)NN * 128];   // aggregation output
__device__ __align__(16) float g_w[(size_t)ETOT * 4];     // exp(e - m) per edge/head
__device__ __align__(16) float g_als[NN * 4];
__device__ __align__(16) float g_ald[NN * 4];
__device__ __align__(16) float g_m[NN * 4];
__device__ __align__(16) float g_s[NN * 4];
__device__ double g_stats[256];                           // [f]=sum, [128+f]=sumsq
__device__ float g_scale[128];
__device__ float g_bias[128];

// ---------------- helpers ---------------------------------------------------
__device__ __forceinline__ float lrelu(float x) { return x > 0.f ? x : 0.2f * x; }

__device__ __forceinline__ void atomicMaxFloat(float* addr, float v) {
    // Works for all finite floats incl. negatives and -0; init must be -inf.
    if (__float_as_int(v) >= 0) {
        atomicMax((int*)addr, __float_as_int(v));
    } else {
        atomicMin((unsigned int*)addr, __float_as_uint(v));
    }
}

__device__ __forceinline__ void redAdd4(float* p, float x, float y, float z, float w) {
    asm volatile("red.global.add.v4.f32 [%0], {%1,%2,%3,%4};"
                 :: "l"(p), "f"(x), "f"(y), "f"(z), "f"(w) : "memory");
}

// ---------------- BN stats ---------------------------------------------------
// Reads either external input (xin != nullptr) with given stride, or g_out.
template <int DOUT>
__global__ void stats_kernel(const float* __restrict__ xin, int stride) {
    const float* in = xin ? xin : g_out;
    constexpr int RPB = 128 / DOUT;      // rows handled per block per step
    int f = threadIdx.x % DOUT;
    int sub = threadIdx.x / DOUT;
    int r = blockIdx.x * RPB + sub;
    int step = gridDim.x * RPB;
    float s = 0.f, q = 0.f;
    for (; r < NN; r += step) {
        float v = in[(size_t)r * stride + f];
        s += v;
        q = fmaf(v, v, q);
    }
    atomicAdd(&g_stats[f], (double)s);
    atomicAdd(&g_stats[128 + f], (double)q);
}

template <int DOUT>
__global__ void bnfin_kernel(const float* __restrict__ g, const float* __restrict__ be) {
    int f = threadIdx.x;
    if (f >= DOUT) return;
    double mu = g_stats[f] / (double)NN;
    double var = g_stats[128 + f] / (double)NN - mu * mu;
    if (var < 0.0) var = 0.0;
    float sc = g[f] * rsqrtf((float)var + 1e-5f);
    g_scale[f] = sc;
    g_bias[f] = be[f] - (float)mu * sc;
    g_stats[f] = 0.0;          // reset for next use (deterministic per-call cycle)
    g_stats[128 + f] = 0.0;
}

// ---------------- zero the aggregation buffer (after GEMM consumed it) ------
template <int DOUT>
__global__ void zero_kernel() {
    size_t i = (size_t)blockIdx.x * blockDim.x + threadIdx.x;
    size_t total = (size_t)NN * DOUT / 4;
    if (i < total) ((float4*)g_out)[i] = make_float4(0.f, 0.f, 0.f, 0.f);
}

// ---------------- GEMM + attention-logit epilogue ----------------------------
// h = act(in) @ W; act(a) = [relu](a*scale[k]+bias[k]).
// Also: al_s/al_d per node+head, init m=-inf, s=0.
template <int DIN, int DOUT, bool RELU>
__global__ void gemm_kernel(const float* __restrict__ xin, int istride,
                            const float* __restrict__ Wg,
                            const float* __restrict__ asg,
                            const float* __restrict__ adg) {
    const float* in = xin ? xin : g_out;
    constexpr int R = DOUT / 32;       // threads per row (each does 32 cols)
    constexpr int ROWS = 256 / R;
    constexpr int C = DOUT / 4;        // channels per head
    constexpr int HPT = 32 / C;        // heads per thread tile

    __shared__ float Ws[DIN * DOUT];
    __shared__ float as_sh[DOUT], ad_sh[DOUT];
    __shared__ float sc_sh[DIN], sb_sh[DIN];

    int tid = threadIdx.x;
    for (int i = tid; i < DIN * DOUT; i += 256) Ws[i] = Wg[i];
    if (tid < DOUT) { as_sh[tid] = asg[tid]; ad_sh[tid] = adg[tid]; }
    if (tid < DIN)  { sc_sh[tid] = g_scale[tid]; sb_sh[tid] = g_bias[tid]; }
    __syncthreads();

    int row = blockIdx.x * ROWS + tid / R;
    int cg  = tid % R;
    if (row >= NN) return;

    float acc[32];
#pragma unroll
    for (int j = 0; j < 32; j++) acc[j] = 0.f;

    const float* irow = in + (size_t)row * istride;
    const float* wp = Ws + cg * 32;
#pragma unroll 4
    for (int k = 0; k < DIN; k++) {
        float a = fmaf(irow[k], sc_sh[k], sb_sh[k]);
        if (RELU) a = fmaxf(a, 0.f);
#pragma unroll
        for (int j = 0; j < 32; j++) acc[j] = fmaf(a, wp[k * DOUT + j], acc[j]);
    }

    // store h tile
    float4* hp = (float4*)(g_h + (size_t)row * DOUT + cg * 32);
#pragma unroll
    for (int q = 0; q < 8; q++) {
        hp[q] = make_float4(acc[4 * q], acc[4 * q + 1], acc[4 * q + 2], acc[4 * q + 3]);
    }

    // attention logits (column tiles align with head boundaries; no atomics)
#pragma unroll
    for (int u = 0; u < HPT; u++) {
        float ss = 0.f, dd = 0.f;
#pragma unroll
        for (int j = 0; j < C; j++) {
            ss = fmaf(acc[u * C + j], as_sh[cg * 32 + u * C + j], ss);
            dd = fmaf(acc[u * C + j], ad_sh[cg * 32 + u * C + j], dd);
        }
        int head = (cg * 32) / C + u;
        g_als[row * 4 + head] = ss;
        g_ald[row * 4 + head] = dd;
    }

    if (cg == 0) {
        float ninf = -__int_as_float(0x7f800000);
        *(float4*)(g_m + row * 4) = make_float4(ninf, ninf, ninf, ninf);
        *(float4*)(g_s + row * 4) = make_float4(0.f, 0.f, 0.f, 0.f);
    }
}

// ---------------- edge pass 1: segment max ----------------------------------
__global__ void edge_max_kernel(const int* __restrict__ ei) {
    int i = blockIdx.x * blockDim.x + threadIdx.x;
    if (i >= ETOT) return;
    int s, d;
    if (i < EE) { s = ei[i]; d = ei[EE + i]; } else { s = i - EE; d = s; }
    float4 a = *(const float4*)(g_als + s * 4);
    float4 b = *(const float4*)(g_ald + d * 4);
    atomicMaxFloat(&g_m[d * 4 + 0], lrelu(a.x + b.x));
    atomicMaxFloat(&g_m[d * 4 + 1], lrelu(a.y + b.y));
    atomicMaxFloat(&g_m[d * 4 + 2], lrelu(a.z + b.z));
    atomicMaxFloat(&g_m[d * 4 + 3], lrelu(a.w + b.w));
}

// ---------------- edge pass 2: exp + segment sum -----------------------------
__global__ void edge_exp_kernel(const int* __restrict__ ei) {
    int i = blockIdx.x * blockDim.x + threadIdx.x;
    if (i >= ETOT) return;
    int s, d;
    if (i < EE) { s = ei[i]; d = ei[EE + i]; } else { s = i - EE; d = s; }
    float4 a = *(const float4*)(g_als + s * 4);
    float4 b = *(const float4*)(g_ald + d * 4);
    float4 m = *(const float4*)(g_m + d * 4);
    float w0 = __expf(lrelu(a.x + b.x) - m.x);
    float w1 = __expf(lrelu(a.y + b.y) - m.y);
    float w2 = __expf(lrelu(a.z + b.z) - m.z);
    float w3 = __expf(lrelu(a.w + b.w) - m.w);
    *(float4*)(g_w + (size_t)i * 4) = make_float4(w0, w1, w2, w3);
    redAdd4(g_s + d * 4, w0, w1, w2, w3);
}

// ---------------- edge pass 3: weighted scatter-aggregate --------------------
template <int DOUT>
__global__ void agg_kernel(const int* __restrict__ ei) {
    constexpr int LPE = DOUT / 4;   // lanes per edge
    constexpr int C = DOUT / 4;     // channels per head
    long long t = (long long)blockIdx.x * blockDim.x + threadIdx.x;
    int edge = (int)(t / LPE);
    int j = (int)(t % LPE);
    int lane = threadIdx.x & 31;
    int leader = lane - j;          // LPE divides 32 and 256 -> groups lane-aligned
    bool valid = edge < ETOT;

    int s = 0, d = 0;
    float a0 = 0.f, a1 = 0.f, a2 = 0.f, a3 = 0.f;
    if (valid && j == 0) {
        if (edge < EE) { s = ei[edge]; d = ei[EE + edge]; } else { s = edge - EE; d = s; }
        float4 w = *(const float4*)(g_w + (size_t)edge * 4);
        float4 sm = *(const float4*)(g_s + d * 4);
        a0 = w.x / (sm.x + 1e-16f);
        a1 = w.y / (sm.y + 1e-16f);
        a2 = w.z / (sm.z + 1e-16f);
        a3 = w.w / (sm.w + 1e-16f);
    }
    s  = __shfl_sync(0xffffffffu, s, leader);
    d  = __shfl_sync(0xffffffffu, d, leader);
    a0 = __shfl_sync(0xffffffffu, a0, leader);
    a1 = __shfl_sync(0xffffffffu, a1, leader);
    a2 = __shfl_sync(0xffffffffu, a2, leader);
    a3 = __shfl_sync(0xffffffffu, a3, leader);
    if (!valid) return;

    float4 hv = *(const float4*)(g_h + (size_t)s * DOUT + 4 * j);
    int head = (4 * j) / C;
    float al = (head == 0) ? a0 : (head == 1) ? a1 : (head == 2) ? a2 : a3;
    redAdd4(g_out + (size_t)d * DOUT + 4 * j, hv.x * al, hv.y * al, hv.z * al, hv.w * al);
}

// ---------------- final: bn+relu+linear(32->1) -------------------------------
__global__ void final_kernel(const float* __restrict__ ow, const float* __restrict__ ob,
                             float* __restrict__ out) {
    int n = blockIdx.x * blockDim.x + threadIdx.x;
    if (n >= NN) return;
    float acc = ob[0];
    const float* row = g_out + (size_t)n * 32;
#pragma unroll
    for (int k = 0; k < 32; k++) {
        float v = fmaxf(fmaf(row[k], g_scale[k], g_bias[k]), 0.f);
        acc = fmaf(v, ow[k], acc);
    }
    out[n] = acc;
}

// ---------------- launch ------------------------------------------------------
extern "C" void kernel_launch(void* const* d_in, const int* in_sizes, int n_in,
                              void* d_out, int out_size) {
    // Detect input ordering:
    //  A (signature):   x, [W,as,ad,b,g,be]x4, g0, be0, ow, ob, edge_index
    //  B (setup dict):  x, edge_index, [W,as,ad,b,g,be]x4, g0, be0, ow, ob
    bool layB = (in_sizes[1] == 2 * EE);
    const float* x = (const float*)d_in[0];
    const int* ei = (const int*)d_in[layB ? 1 : (n_in - 1)];
    int base = layB ? 2 : 1;
    const float *W[4], *As[4], *Ad[4], *G[4], *Be[4];
    for (int l = 0; l < 4; l++) {
        int b = base + 6 * l;
        W[l]  = (const float*)d_in[b];
        As[l] = (const float*)d_in[b + 1];
        Ad[l] = (const float*)d_in[b + 2];
        // d_in[b+3] = bias: cancels inside BatchNorm, unused
        G[l]  = (const float*)d_in[b + 4];
        Be[l] = (const float*)d_in[b + 5];
    }
    int tb = base + 24;
    const float* g0  = (const float*)d_in[tb];
    const float* be0 = (const float*)d_in[tb + 1];
    const float* ow  = (const float*)d_in[tb + 2];
    const float* ob  = (const float*)d_in[tb + 3];
    float* out = (float*)d_out;

    const int TPB = 256;
    int egrid = (ETOT + TPB - 1) / TPB;

    // input BN (x[:, :4], stride 22)
    stats_kernel<4><<<1024, 128>>>(x, 22);
    bnfin_kernel<4><<<1, 4>>>(g0, be0);

    // ---- layer 1: 4 -> 64 (no relu on input)
    gemm_kernel<4, 64, false><<<(NN + 127) / 128, 256>>>(x, 22, W[0], As[0], Ad[0]);
    zero_kernel<64><<<(NN * 16 + TPB - 1) / TPB, TPB>>>();
    edge_max_kernel<<<egrid, TPB>>>(ei);
    edge_exp_kernel<<<egrid, TPB>>>(ei);
    agg_kernel<64><<<(int)(((long long)ETOT * 16 + TPB - 1) / TPB), TPB>>>(ei);
    stats_kernel<64><<<1024, 128>>>(nullptr, 64);
    bnfin_kernel<64><<<1, 64>>>(G[0], Be[0]);

    // ---- layer 2: 64 -> 128
    gemm_kernel<64, 128, true><<<(NN + 63) / 64, 256>>>(nullptr, 64, W[1], As[1], Ad[1]);
    zero_kernel<128><<<(NN * 32 + TPB - 1) / TPB, TPB>>>();
    edge_max_kernel<<<egrid, TPB>>>(ei);
    edge_exp_kernel<<<egrid, TPB>>>(ei);
    agg_kernel<128><<<(int)(((long long)ETOT * 32 + TPB - 1) / TPB), TPB>>>(ei);
    stats_kernel<128><<<1024, 128>>>(nullptr, 128);
    bnfin_kernel<128><<<1, 128>>>(G[1], Be[1]);

    // ---- layer 3: 128 -> 64
    gemm_kernel<128, 64, true><<<(NN + 127) / 128, 256>>>(nullptr, 128, W[2], As[2], Ad[2]);
    zero_kernel<64><<<(NN * 16 + TPB - 1) / TPB, TPB>>>();
    edge_max_kernel<<<egrid, TPB>>>(ei);
    edge_exp_kernel<<<egrid, TPB>>>(ei);
    agg_kernel<64><<<(int)(((long long)ETOT * 16 + TPB - 1) / TPB), TPB>>>(ei);
    stats_kernel<64><<<1024, 128>>>(nullptr, 64);
    bnfin_kernel<64><<<1, 64>>>(G[2], Be[2]);

    // ---- layer 4: 64 -> 32
    gemm_kernel<64, 32, true><<<(NN + 255) / 256, 256>>>(nullptr, 64, W[3], As[3], Ad[3]);
    zero_kernel<32><<<(NN * 8 + TPB - 1) / TPB, TPB>>>();
    edge_max_kernel<<<egrid, TPB>>>(ei);
    edge_exp_kernel<<<egrid, TPB>>>(ei);
    agg_kernel<32><<<(int)(((long long)ETOT * 8 + TPB - 1) / TPB), TPB>>>(ei);
    stats_kernel<32><<<1024, 128>>>(nullptr, 32);
    bnfin_kernel<32><<<1, 32>>>(G[3], Be[3]);

    // ---- output head
    final_kernel<<<(NN + 255) / 256, 256>>>(ow, ob, out);
}

// round 3
// speedup vs baseline: 1.4024x; 1.4024x over previous
#include <cuda_runtime.h>
#include <cstdint>
#include <cstddef>
#include <math.h>

#define NN 100000
#define EE 1600000

// ---------------- scratch (device globals; no runtime allocation) ----------
__device__ __align__(16) float g_h[(size_t)NN * 128];     // GEMM output (per layer)
__device__ __align__(16) float g_out[(size_t)NN * 128];   // aggregation output
__device__ __align__(16) float g_als[NN * 4];
__device__ __align__(16) float g_ald[NN * 4];
__device__ double g_stats[256];                           // [f]=sum, [128+f]=sumsq
__device__ float g_scale[128];
__device__ float g_bias[128];
// CSR (dst-sorted)
__device__ int g_cnt[NN];
__device__ int g_rowptr[NN + 1];
__device__ int g_pos[NN];
__device__ int g_col[EE];

// ---------------- helpers ---------------------------------------------------
__device__ __forceinline__ float lrelu(float x) { return x > 0.f ? x : 0.2f * x; }

// ---------------- CSR build --------------------------------------------------
__global__ void zero_cnt_kernel() {
    int i = blockIdx.x * blockDim.x + threadIdx.x;
    if (i < NN) g_cnt[i] = 0;
}

__global__ void hist_kernel(const int* __restrict__ ei) {
    int i = blockIdx.x * blockDim.x + threadIdx.x;
    if (i < EE) atomicAdd(&g_cnt[ei[EE + i]], 1);
}

__global__ void scan_kernel() {
    __shared__ int sh[1024];
    const int T = 1024;
    const int per = (NN + T - 1) / T;
    int t = threadIdx.x;
    int begin = t * per;
    int end = begin + per; if (end > NN) end = NN;
    int sum = 0;
    for (int i = begin; i < end; i++) sum += g_cnt[i];
    sh[t] = sum;
    __syncthreads();
    for (int off = 1; off < T; off <<= 1) {
        int v = (t >= off) ? sh[t - off] : 0;
        __syncthreads();
        sh[t] += v;
        __syncthreads();
    }
    int run = (t == 0) ? 0 : sh[t - 1];
    for (int i = begin; i < end; i++) {
        int c = g_cnt[i];
        g_rowptr[i] = run;
        g_pos[i] = run;
        run += c;
    }
    if (t == T - 1) g_rowptr[NN] = run;
}

__global__ void scatter_kernel(const int* __restrict__ ei) {
    int i = blockIdx.x * blockDim.x + threadIdx.x;
    if (i >= EE) return;
    int d = ei[EE + i];
    int p = atomicAdd(&g_pos[d], 1);
    g_col[p] = ei[i];
}

// ---------------- BN stats ---------------------------------------------------
template <int DOUT>
__global__ void stats_kernel(const float* __restrict__ xin, int stride) {
    const float* in = xin ? xin : g_out;
    constexpr int RPB = 128 / DOUT;
    int f = threadIdx.x % DOUT;
    int sub = threadIdx.x / DOUT;
    int r = blockIdx.x * RPB + sub;
    int step = gridDim.x * RPB;
    float s = 0.f, q = 0.f;
    for (; r < NN; r += step) {
        float v = in[(size_t)r * stride + f];
        s += v;
        q = fmaf(v, v, q);
    }
    atomicAdd(&g_stats[f], (double)s);
    atomicAdd(&g_stats[128 + f], (double)q);
}

template <int DOUT>
__global__ void bnfin_kernel(const float* __restrict__ g, const float* __restrict__ be) {
    int f = threadIdx.x;
    if (f >= DOUT) return;
    double mu = g_stats[f] / (double)NN;
    double var = g_stats[128 + f] / (double)NN - mu * mu;
    if (var < 0.0) var = 0.0;
    float sc = g[f] * rsqrtf((float)var + 1e-5f);
    g_scale[f] = sc;
    g_bias[f] = be[f] - (float)mu * sc;
    g_stats[f] = 0.0;
    g_stats[128 + f] = 0.0;
}

// ---------------- GEMM + attention-logit epilogue ----------------------------
template <int DIN, int DOUT, bool RELU>
__global__ void gemm_kernel(const float* __restrict__ xin, int istride,
                            const float* __restrict__ Wg,
                            const float* __restrict__ asg,
                            const float* __restrict__ adg) {
    const float* in = xin ? xin : g_out;
    constexpr int R = DOUT / 32;
    constexpr int ROWS = 256 / R;
    constexpr int C = DOUT / 4;
    constexpr int HPT = 32 / C;

    __shared__ float Ws[DIN * DOUT];
    __shared__ float as_sh[DOUT], ad_sh[DOUT];
    __shared__ float sc_sh[DIN], sb_sh[DIN];

    int tid = threadIdx.x;
    for (int i = tid; i < DIN * DOUT; i += 256) Ws[i] = Wg[i];
    if (tid < DOUT) { as_sh[tid] = asg[tid]; ad_sh[tid] = adg[tid]; }
    if (tid < DIN)  { sc_sh[tid] = g_scale[tid]; sb_sh[tid] = g_bias[tid]; }
    __syncthreads();

    int row = blockIdx.x * ROWS + tid / R;
    int cg  = tid % R;
    if (row >= NN) return;

    float acc[32];
#pragma unroll
    for (int j = 0; j < 32; j++) acc[j] = 0.f;

    const float* irow = in + (size_t)row * istride;
    const float* wp = Ws + cg * 32;
#pragma unroll 4
    for (int k = 0; k < DIN; k++) {
        float a = fmaf(irow[k], sc_sh[k], sb_sh[k]);
        if (RELU) a = fmaxf(a, 0.f);
#pragma unroll
        for (int j = 0; j < 32; j++) acc[j] = fmaf(a, wp[k * DOUT + j], acc[j]);
    }

    float4* hp = (float4*)(g_h + (size_t)row * DOUT + cg * 32);
#pragma unroll
    for (int q = 0; q < 8; q++)
        hp[q] = make_float4(acc[4 * q], acc[4 * q + 1], acc[4 * q + 2], acc[4 * q + 3]);

#pragma unroll
    for (int u = 0; u < HPT; u++) {
        float ss = 0.f, dd = 0.f;
#pragma unroll
        for (int j = 0; j < C; j++) {
            ss = fmaf(acc[u * C + j], as_sh[cg * 32 + u * C + j], ss);
            dd = fmaf(acc[u * C + j], ad_sh[cg * 32 + u * C + j], dd);
        }
        int head = (cg * 32) / C + u;
        g_als[row * 4 + head] = ss;
        g_ald[row * 4 + head] = dd;
    }
}

// ---------------- fused softmax + aggregation: one warp per dst node --------
template <int DOUT>
__global__ void agg_node_kernel() {
    constexpr int C   = DOUT / 4;   // channels per head
    constexpr int LPE = DOUT / 4;   // lanes per edge (each lane: 4 channels)
    constexpr int EPW = 32 / LPE;   // edges in flight per warp

    int warp = (blockIdx.x * blockDim.x + threadIdx.x) >> 5;
    int lane = threadIdx.x & 31;
    if (warp >= NN) return;
    int n = warp;
    int start = g_rowptr[n];
    int deg = g_rowptr[n + 1] - start;   // self-loop handled as extra edge i==deg

    float4 ald4 = *(const float4*)(g_ald + n * 4);

    // pass A: segment max per head
    const float NINF = -__int_as_float(0x7f800000);
    float4 m4 = make_float4(NINF, NINF, NINF, NINF);
    for (int i = lane; i <= deg; i += 32) {
        int s = (i < deg) ? g_col[start + i] : n;
        float4 a = *(const float4*)(g_als + s * 4);
        m4.x = fmaxf(m4.x, lrelu(a.x + ald4.x));
        m4.y = fmaxf(m4.y, lrelu(a.y + ald4.y));
        m4.z = fmaxf(m4.z, lrelu(a.z + ald4.z));
        m4.w = fmaxf(m4.w, lrelu(a.w + ald4.w));
    }
#pragma unroll
    for (int off = 16; off >= 1; off >>= 1) {
        m4.x = fmaxf(m4.x, __shfl_xor_sync(0xffffffffu, m4.x, off));
        m4.y = fmaxf(m4.y, __shfl_xor_sync(0xffffffffu, m4.y, off));
        m4.z = fmaxf(m4.z, __shfl_xor_sync(0xffffffffu, m4.z, off));
        m4.w = fmaxf(m4.w, __shfl_xor_sync(0xffffffffu, m4.w, off));
    }

    // pass B: exp-sum per head
    float4 s4 = make_float4(0.f, 0.f, 0.f, 0.f);
    for (int i = lane; i <= deg; i += 32) {
        int s = (i < deg) ? g_col[start + i] : n;
        float4 a = *(const float4*)(g_als + s * 4);
        s4.x += __expf(lrelu(a.x + ald4.x) - m4.x);
        s4.y += __expf(lrelu(a.y + ald4.y) - m4.y);
        s4.z += __expf(lrelu(a.z + ald4.z) - m4.z);
        s4.w += __expf(lrelu(a.w + ald4.w) - m4.w);
    }
#pragma unroll
    for (int off = 16; off >= 1; off >>= 1) {
        s4.x += __shfl_xor_sync(0xffffffffu, s4.x, off);
        s4.y += __shfl_xor_sync(0xffffffffu, s4.y, off);
        s4.z += __shfl_xor_sync(0xffffffffu, s4.z, off);
        s4.w += __shfl_xor_sync(0xffffffffu, s4.w, off);
    }
    float4 inv4 = make_float4(1.f / (s4.x + 1e-16f), 1.f / (s4.y + 1e-16f),
                              1.f / (s4.z + 1e-16f), 1.f / (s4.w + 1e-16f));

    // per-lane head-scalar constants
    int cl = lane % LPE;                 // channel-group within edge
    int sg = lane / LPE;                 // subgroup (edge slot)
    int head = (cl * 4) / C;
    float mh   = (head == 0) ? m4.x   : (head == 1) ? m4.y   : (head == 2) ? m4.z   : m4.w;
    float invh = (head == 0) ? inv4.x : (head == 1) ? inv4.y : (head == 2) ? inv4.z : inv4.w;
    float aldh = (head == 0) ? ald4.x : (head == 1) ? ald4.y : (head == 2) ? ald4.z : ald4.w;

    // pass C: gather h[src]*alpha, accumulate in registers
    float4 acc = make_float4(0.f, 0.f, 0.f, 0.f);
    for (int i = sg; i <= deg; i += EPW) {
        int s = (i < deg) ? g_col[start + i] : n;
        float av = __ldg(&g_als[s * 4 + head]);
        float alpha = __expf(lrelu(av + aldh) - mh) * invh;
        float4 hv = *(const float4*)(g_h + (size_t)s * DOUT + cl * 4);
        acc.x = fmaf(hv.x, alpha, acc.x);
        acc.y = fmaf(hv.y, alpha, acc.y);
        acc.z = fmaf(hv.z, alpha, acc.z);
        acc.w = fmaf(hv.w, alpha, acc.w);
    }
    __syncwarp();
#pragma unroll
    for (int off = LPE; off < 32; off <<= 1) {
        acc.x += __shfl_xor_sync(0xffffffffu, acc.x, off);
        acc.y += __shfl_xor_sync(0xffffffffu, acc.y, off);
        acc.z += __shfl_xor_sync(0xffffffffu, acc.z, off);
        acc.w += __shfl_xor_sync(0xffffffffu, acc.w, off);
    }
    if (lane < LPE)
        *(float4*)(g_out + (size_t)n * DOUT + lane * 4) = acc;
}

// ---------------- final: bn+relu+linear(32->1) -------------------------------
__global__ void final_kernel(const float* __restrict__ ow, const float* __restrict__ ob,
                             float* __restrict__ out) {
    int n = blockIdx.x * blockDim.x + threadIdx.x;
    if (n >= NN) return;
    float acc = ob[0];
    const float* row = g_out + (size_t)n * 32;
#pragma unroll
    for (int k = 0; k < 32; k++) {
        float v = fmaxf(fmaf(row[k], g_scale[k], g_bias[k]), 0.f);
        acc = fmaf(v, ow[k], acc);
    }
    out[n] = acc;
}

// ---------------- launch ------------------------------------------------------
extern "C" void kernel_launch(void* const* d_in, const int* in_sizes, int n_in,
                              void* d_out, int out_size) {
    bool layB = (in_sizes[1] == 2 * EE);
    const float* x = (const float*)d_in[0];
    const int* ei = (const int*)d_in[layB ? 1 : (n_in - 1)];
    int base = layB ? 2 : 1;
    const float *W[4], *As[4], *Ad[4], *G[4], *Be[4];
    for (int l = 0; l < 4; l++) {
        int b = base + 6 * l;
        W[l]  = (const float*)d_in[b];
        As[l] = (const float*)d_in[b + 1];
        Ad[l] = (const float*)d_in[b + 2];
        G[l]  = (const float*)d_in[b + 4];
        Be[l] = (const float*)d_in[b + 5];
    }
    int tb = base + 24;
    const float* g0  = (const float*)d_in[tb];
    const float* be0 = (const float*)d_in[tb + 1];
    const float* ow  = (const float*)d_in[tb + 2];
    const float* ob  = (const float*)d_in[tb + 3];
    float* out = (float*)d_out;

    const int TPB = 256;
    int egrid = (EE + TPB - 1) / TPB;
    int ngrid_warp = (NN * 32 + TPB - 1) / TPB;   // warp per node

    // ---- CSR build (once; edges shared by all layers)
    zero_cnt_kernel<<<(NN + TPB - 1) / TPB, TPB>>>();
    hist_kernel<<<egrid, TPB>>>(ei);
    scan_kernel<<<1, 1024>>>();
    scatter_kernel<<<egrid, TPB>>>(ei);

    // ---- input BN (x[:, :4], stride 22)
    stats_kernel<4><<<1024, 128>>>(x, 22);
    bnfin_kernel<4><<<1, 4>>>(g0, be0);

    // ---- layer 1: 4 -> 64
    gemm_kernel<4, 64, false><<<(NN + 127) / 128, 256>>>(x, 22, W[0], As[0], Ad[0]);
    agg_node_kernel<64><<<ngrid_warp, TPB>>>();
    stats_kernel<64><<<1024, 128>>>(nullptr, 64);
    bnfin_kernel<64><<<1, 64>>>(G[0], Be[0]);

    // ---- layer 2: 64 -> 128
    gemm_kernel<64, 128, true><<<(NN + 63) / 64, 256>>>(nullptr, 64, W[1], As[1], Ad[1]);
    agg_node_kernel<128><<<ngrid_warp, TPB>>>();
    stats_kernel<128><<<1024, 128>>>(nullptr, 128);
    bnfin_kernel<128><<<1, 128>>>(G[1], Be[1]);

    // ---- layer 3: 128 -> 64
    gemm_kernel<128, 64, true><<<(NN + 127) / 128, 256>>>(nullptr, 128, W[2], As[2], Ad[2]);
    agg_node_kernel<64><<<ngrid_warp, TPB>>>();
    stats_kernel<64><<<1024, 128>>>(nullptr, 64);
    bnfin_kernel<64><<<1, 64>>>(G[2], Be[2]);

    // ---- layer 4: 64 -> 32
    gemm_kernel<64, 32, true><<<(NN + 255) / 256, 256>>>(nullptr, 64, W[3], As[3], Ad[3]);
    agg_node_kernel<32><<<ngrid_warp, TPB>>>();
    stats_kernel<32><<<1024, 128>>>(nullptr, 32);
    bnfin_kernel<32><<<1, 32>>>(G[3], Be[3]);

    // ---- output head
    final_kernel<<<(NN + 255) / 256, 256>>>(ow, ob, out);
}